// round 9
// baseline (speedup 1.0000x reference)
#include <cuda_runtime.h>

#define N_NODES 100000
#define N_EDGES 3200000
#define D_IN    128
#define D_HID   16
#define N_CLS   2

#define NB_SCAN 391          // 391 * 256 = 100096 >= N_NODES

// ---- scratch (static device memory; no runtime allocation) ----
// g_cnt starts zero (module init) and is re-zeroed by k_gather2 every pass,
// so each graph replay sees identical state.
__device__ __align__(128) int   g_cnt [N_NODES];
__device__ __align__(128) int   g_ptr [N_NODES];
__device__ __align__(128) int   g_fill[N_NODES];
__device__ __align__(128) float g_dinv[N_NODES];
__device__ __align__(128) int   g_csr_src[N_EDGES];
__device__ __align__(128) float g_g1  [N_NODES * D_HID];
__device__ __align__(128) float g_g2  [N_NODES * N_CLS];

// decoupled-lookback scan state (all module-init 0; self-reset each pass)
__device__ volatile int g_flag[NB_SCAN];   // 0 none, 1 aggregate ready, 2 inclusive ready
__device__ volatile int g_agg [NB_SCAN];
__device__ volatile int g_inc [NB_SCAN];
__device__ int g_done;

// ---- 1) in-degree histogram (4 edges per thread, vector index load) ----
__global__ __launch_bounds__(256) void k_cnt(const int* __restrict__ ei_dst) {
    int t = blockIdx.x * blockDim.x + threadIdx.x;     // 800000 threads
    int4 d = *reinterpret_cast<const int4*>(&ei_dst[t * 4]);
    atomicAdd(&g_cnt[d.x], 1);
    atomicAdd(&g_cnt[d.y], 1);
    atomicAdd(&g_cnt[d.z], 1);
    atomicAdd(&g_cnt[d.w], 1);
}

// ---- 2) single-pass exclusive scan (decoupled lookback) + dinv + fill init ----
__global__ __launch_bounds__(256) void k_scan() {
    __shared__ int wsum[8];
    __shared__ int s_base;
    __shared__ int s_last;
    int b = blockIdx.x, t = threadIdx.x;
    int i = b * 256 + t;
    int lane = t & 31, w = t >> 5;

    int v = (i < N_NODES) ? g_cnt[i] : 0;

    // warp inclusive scan
    int x = v;
#pragma unroll
    for (int off = 1; off < 32; off <<= 1) {
        int y = __shfl_up_sync(0xffffffffu, x, off);
        if (lane >= off) x += y;
    }
    if (lane == 31) wsum[w] = x;
    __syncthreads();
    if (w == 0) {
        int s = (lane < 8) ? wsum[lane] : 0;
#pragma unroll
        for (int off = 1; off < 8; off <<= 1) {
            int y = __shfl_up_sync(0xffffffffu, s, off);
            if (lane >= off) s += y;
        }
        if (lane < 8) wsum[lane] = s;
    }
    __syncthreads();
    int incl  = x + (w > 0 ? wsum[w - 1] : 0);   // block-local inclusive
    int total = wsum[7];

    // publish aggregate, look back for exclusive base, publish inclusive
    if (t == 0) {
        if (b == 0) {
            g_inc[0] = total;
            __threadfence();
            g_flag[0] = 2;
            s_base = 0;
        } else {
            g_agg[b] = total;
            __threadfence();
            g_flag[b] = 1;
            int base = 0;
            for (int j = b - 1; j >= 0; ) {
                int f;
                while ((f = g_flag[j]) == 0) { }
                __threadfence();
                if (f == 2) { base += g_inc[j]; break; }
                base += g_agg[j];
                j--;
            }
            g_inc[b] = base + total;
            __threadfence();
            g_flag[b] = 2;
            s_base = base;
        }
    }
    __syncthreads();

    if (i < N_NODES) {
        int excl = s_base + incl - v;
        g_ptr[i]  = excl;
        g_fill[i] = excl;
        g_dinv[i] = rsqrtf((float)(v + 1));      // +1 self-loop
    }

    // deterministic self-reset: last block to finish clears lookback state
    __syncthreads();
    if (t == 0) s_last = (atomicAdd(&g_done, 1) == NB_SCAN - 1);
    __syncthreads();
    if (s_last) {
        for (int j = t; j < NB_SCAN; j += 256) g_flag[j] = 0;
        if (t == 0) g_done = 0;
    }
}

// ---- 3) g1 = (x @ W1) * dinv ----
__global__ __launch_bounds__(256) void k_gemm1(const float* __restrict__ x,
                                               const float* __restrict__ W1) {
    __shared__ float Ws[D_IN * D_HID];
    __shared__ float Xs[16][D_IN + 1];
    int tid = threadIdx.x;
    int nodeBase = blockIdx.x * 16;

    for (int i = tid; i < D_IN * D_HID; i += 256) Ws[i] = W1[i];
    for (int i = tid; i < 16 * D_IN; i += 256) {
        int r = i >> 7, c = i & 127;
        Xs[r][c] = x[(nodeBase + r) * D_IN + c];
    }
    __syncthreads();

    int node = tid >> 4, col = tid & 15;
    float acc = 0.f;
#pragma unroll
    for (int k = 0; k < D_IN; k++) acc += Xs[node][k] * Ws[k * D_HID + col];

    int gn = nodeBase + node;
    g_g1[gn * D_HID + col] = acc * g_dinv[gn];
}

// ---- 4) fill CSR (4 edges per thread, vector index loads) ----
__global__ __launch_bounds__(256) void k_fill(const int* __restrict__ ei_src,
                                              const int* __restrict__ ei_dst) {
    int t = blockIdx.x * blockDim.x + threadIdx.x;     // 800000 threads
    int4 s = *reinterpret_cast<const int4*>(&ei_src[t * 4]);
    int4 d = *reinterpret_cast<const int4*>(&ei_dst[t * 4]);
    g_csr_src[atomicAdd(&g_fill[d.x], 1)] = s.x;
    g_csr_src[atomicAdd(&g_fill[d.y], 1)] = s.y;
    g_csr_src[atomicAdd(&g_fill[d.z], 1)] = s.z;
    g_csr_src[atomicAdd(&g_fill[d.w], 1)] = s.w;
}

// ---- 5) layer-1 gather + fused layer-2 node GEMM ----
// warp per node; 4 lanes per edge (one coalesced 64B row), 8 edges/iter, x2 unroll.
__global__ __launch_bounds__(256) void k_gather1(const float* __restrict__ b1,
                                                 const float* __restrict__ W2) {
    int n    = (blockIdx.x * blockDim.x + threadIdx.x) >> 5;
    int lane = threadIdx.x & 31;
    int g    = lane >> 2;        // edge group 0..7
    int q    = lane & 3;         // quad: dims q*4 .. q*4+3

    int ptr = g_ptr[n];
    int deg = g_cnt[n];

    float4 acc = make_float4(0.f, 0.f, 0.f, 0.f);
    if (g == 0)                                              // self-loop
        acc = *reinterpret_cast<const float4*>(&g_g1[n * D_HID + q * 4]);

    int i = g;
    for (; i + 8 < deg; i += 16) {
        int s0 = g_csr_src[ptr + i];
        int s1 = g_csr_src[ptr + i + 8];
        float4 r0 = *reinterpret_cast<const float4*>(&g_g1[s0 * D_HID + q * 4]);
        float4 r1 = *reinterpret_cast<const float4*>(&g_g1[s1 * D_HID + q * 4]);
        acc.x += r0.x + r1.x; acc.y += r0.y + r1.y;
        acc.z += r0.z + r1.z; acc.w += r0.w + r1.w;
    }
    if (i < deg) {
        int s = g_csr_src[ptr + i];
        float4 r = *reinterpret_cast<const float4*>(&g_g1[s * D_HID + q * 4]);
        acc.x += r.x; acc.y += r.y; acc.z += r.z; acc.w += r.w;
    }

#pragma unroll
    for (int off = 16; off >= 4; off >>= 1) {
        acc.x += __shfl_down_sync(0xffffffffu, acc.x, off);
        acc.y += __shfl_down_sync(0xffffffffu, acc.y, off);
        acc.z += __shfl_down_sync(0xffffffffu, acc.z, off);
        acc.w += __shfl_down_sync(0xffffffffu, acc.w, off);
    }
    float dv = g_dinv[n];
    float4 bq = *reinterpret_cast<const float4*>(&b1[q * 4]);
    float t0 = fmaxf(fmaf(dv, acc.x, bq.x), 0.f);
    float t1 = fmaxf(fmaf(dv, acc.y, bq.y), 0.f);
    float t2 = fmaxf(fmaf(dv, acc.z, bq.z), 0.f);
    float t3 = fmaxf(fmaf(dv, acc.w, bq.w), 0.f);
    float4 w0 = *reinterpret_cast<const float4*>(&W2[q * 8]);
    float4 w1 = *reinterpret_cast<const float4*>(&W2[q * 8 + 4]);
    float p0 = fmaf(t0, w0.x, fmaf(t1, w0.z, fmaf(t2, w1.x, t3 * w1.z)));
    float p1 = fmaf(t0, w0.y, fmaf(t1, w0.w, fmaf(t2, w1.y, t3 * w1.w)));
    p0 += __shfl_down_sync(0xffffffffu, p0, 2);
    p1 += __shfl_down_sync(0xffffffffu, p1, 2);
    p0 += __shfl_down_sync(0xffffffffu, p0, 1);
    p1 += __shfl_down_sync(0xffffffffu, p1, 1);
    if (lane == 0)
        *reinterpret_cast<float2*>(&g_g2[n * 2]) = make_float2(p0 * dv, p1 * dv);
}

// ---- 6) layer-2 gather + fused log_softmax + g_cnt self-reset ----
__global__ __launch_bounds__(256) void k_gather2(const float* __restrict__ b2,
                                                 float* __restrict__ out) {
    int n    = (blockIdx.x * blockDim.x + threadIdx.x) >> 5;
    int lane = threadIdx.x & 31;
    int c = lane & 1;

    int ptr = g_ptr[n];
    int deg = g_cnt[n];

    float acc = (lane < 2) ? g_g2[n * 2 + c] : 0.f;          // self-loop
    int i = lane >> 1;
    for (; i + 16 < deg; i += 32) {
        int s0 = g_csr_src[ptr + i];
        int s1 = g_csr_src[ptr + i + 16];
        acc += g_g2[s0 * 2 + c] + g_g2[s1 * 2 + c];
    }
    if (i < deg) {
        int s = g_csr_src[ptr + i];
        acc += g_g2[s * 2 + c];
    }
#pragma unroll
    for (int off = 16; off >= 2; off >>= 1)
        acc += __shfl_down_sync(0xffffffffu, acc, off);       // parity preserved

    float dv = g_dinv[n];
    float z = fmaf(dv, acc, __ldg(&b2[c]));                   // valid on lanes 0,1
    float z0 = __shfl_sync(0xffffffffu, z, 0);
    float z1 = __shfl_sync(0xffffffffu, z, 1);
    if (lane == 0) {
        float m = fmaxf(z0, z1);
        float lse = m + logf(expf(z0 - m) + expf(z1 - m));
        *reinterpret_cast<float2*>(&out[n * 2]) = make_float2(z0 - lse, z1 - lse);
        g_cnt[n] = 0;                                         // reset for next replay
    }
}

extern "C" void kernel_launch(void* const* d_in, const int* in_sizes, int n_in,
                              void* d_out, int out_size) {
    const float* x      = (const float*)d_in[0];
    const int*   ei     = (const int*)d_in[1];      // int32 [2, E]
    const int*   ei_src = ei;
    const int*   ei_dst = ei + N_EDGES;
    const float* W1     = (const float*)d_in[2];
    const float* b1     = (const float*)d_in[3];
    const float* W2     = (const float*)d_in[4];
    const float* b2     = (const float*)d_in[5];
    float* out = (float*)d_out;

    k_cnt    <<<N_EDGES / 4 / 256, 256>>>(ei_dst);      // 3125 blocks
    k_scan   <<<NB_SCAN, 256>>>();
    k_gemm1  <<<N_NODES / 16, 256>>>(x, W1);
    k_fill   <<<N_EDGES / 4 / 256, 256>>>(ei_src, ei_dst);
    k_gather1<<<N_NODES / 8, 256>>>(b1, W2);
    k_gather2<<<N_NODES / 8, 256>>>(b2, out);
}

// round 10
// speedup vs baseline: 1.1731x; 1.1731x over previous
#include <cuda_runtime.h>

#define N_NODES 100000
#define N_EDGES 3200000
#define D_IN    128
#define D_HID   16
#define N_CLS   2

#define NB_SCAN 391          // 391 * 256 = 100096 >= N_NODES

// ---- scratch (static device memory; no runtime allocation) ----
// g_cnt starts zero (module init) and is re-zeroed by k_gather2 every pass.
__device__ __align__(128) int   g_cnt [N_NODES];
__device__ __align__(128) int   g_ptr [N_NODES];
__device__ __align__(128) int   g_fill[N_NODES];
__device__ __align__(128) float g_dinv[N_NODES];
__device__ __align__(128) int   g_csr_src[N_EDGES];
__device__ __align__(128) float g_g1  [N_NODES * D_HID];
__device__ __align__(128) float g_g2  [N_NODES * N_CLS];

// scan state (module-init 0; self-reset every pass)
__device__ __align__(128) int g_agg[NB_SCAN];
__device__ volatile int g_pub;    // blocks that have published their aggregate
__device__ int g_fin;             // blocks fully done (for reset)

// ---- 1) in-degree histogram (1 edge/thread; unused return -> RED) ----
__global__ __launch_bounds__(256) void k_cnt(const int* __restrict__ ei_dst) {
    int e = blockIdx.x * blockDim.x + threadIdx.x;
    if (e < N_EDGES) atomicAdd(&g_cnt[ei_dst[e]], 1);
}

// ---- 2) single-kernel exclusive scan: publish-all + spin + parallel sum ----
__global__ __launch_bounds__(256) void k_scan() {
    __shared__ int wsum[8];
    __shared__ int red[8];
    __shared__ int s_base;
    __shared__ int s_last;
    int b = blockIdx.x, t = threadIdx.x;
    int i = b * 256 + t;
    int lane = t & 31, w = t >> 5;

    int v = (i < N_NODES) ? g_cnt[i] : 0;

    // block-local inclusive scan (warp shuffle + warp-of-warps)
    int x = v;
#pragma unroll
    for (int off = 1; off < 32; off <<= 1) {
        int y = __shfl_up_sync(0xffffffffu, x, off);
        if (lane >= off) x += y;
    }
    if (lane == 31) wsum[w] = x;
    __syncthreads();
    if (w == 0) {
        int s = (lane < 8) ? wsum[lane] : 0;
#pragma unroll
        for (int off = 1; off < 8; off <<= 1) {
            int y = __shfl_up_sync(0xffffffffu, s, off);
            if (lane >= off) s += y;
        }
        if (lane < 8) wsum[lane] = s;
    }
    __syncthreads();
    int incl  = x + (w > 0 ? wsum[w - 1] : 0);
    int total = wsum[7];

    // publish aggregate; wait until ALL blocks published (all co-resident: 391 CTAs)
    if (t == 0) {
        g_agg[b] = total;
        __threadfence();
        atomicAdd((int*)&g_pub, 1);
        while (g_pub < NB_SCAN) { }
    }
    __syncthreads();

    // base = sum of aggregates of blocks 0..b-1 (cooperative, coalesced)
    int part = 0;
    for (int j = t; j < b; j += 256) part += g_agg[j];
#pragma unroll
    for (int off = 16; off >= 1; off >>= 1)
        part += __shfl_down_sync(0xffffffffu, part, off);
    if (lane == 0) red[w] = part;
    __syncthreads();
    if (t == 0) {
        int base = 0;
#pragma unroll
        for (int k = 0; k < 8; k++) base += red[k];
        s_base = base;
    }
    __syncthreads();

    if (i < N_NODES) {
        int excl = s_base + incl - v;
        g_ptr[i]  = excl;
        g_fill[i] = excl;
        g_dinv[i] = rsqrtf((float)(v + 1));      // +1 self-loop
    }

    // deterministic self-reset: last finishing block clears counters.
    // g_fin increments only after this block exited the spin, so when the
    // last block resets g_pub nobody can still be spinning.
    __syncthreads();
    if (t == 0) s_last = (atomicAdd(&g_fin, 1) == NB_SCAN - 1);
    __syncthreads();
    if (s_last && t == 0) { g_fin = 0; g_pub = 0; }
}

// ---- 3) g1 = (x @ W1) * dinv ----
__global__ __launch_bounds__(256) void k_gemm1(const float* __restrict__ x,
                                               const float* __restrict__ W1) {
    __shared__ float Ws[D_IN * D_HID];
    __shared__ float Xs[16][D_IN + 1];
    int tid = threadIdx.x;
    int nodeBase = blockIdx.x * 16;

    for (int i = tid; i < D_IN * D_HID; i += 256) Ws[i] = W1[i];
    for (int i = tid; i < 16 * D_IN; i += 256) {
        int r = i >> 7, c = i & 127;
        Xs[r][c] = x[(nodeBase + r) * D_IN + c];
    }
    __syncthreads();

    int node = tid >> 4, col = tid & 15;
    float acc = 0.f;
#pragma unroll
    for (int k = 0; k < D_IN; k++) acc += Xs[node][k] * Ws[k * D_HID + col];

    int gn = nodeBase + node;
    g_g1[gn * D_HID + col] = acc * g_dinv[gn];
}

// ---- 4) fill CSR (1 edge/thread, max memory-level parallelism) ----
__global__ __launch_bounds__(256) void k_fill(const int* __restrict__ ei_src,
                                              const int* __restrict__ ei_dst) {
    int e = blockIdx.x * blockDim.x + threadIdx.x;
    if (e >= N_EDGES) return;
    int pos = atomicAdd(&g_fill[ei_dst[e]], 1);
    g_csr_src[pos] = ei_src[e];
}

// ---- 5) layer-1 gather + fused layer-2 node GEMM ----
// warp per node; 4 lanes per edge (one coalesced 64B row), 8 edges/iter, x2 unroll.
__global__ __launch_bounds__(256) void k_gather1(const float* __restrict__ b1,
                                                 const float* __restrict__ W2) {
    int n    = (blockIdx.x * blockDim.x + threadIdx.x) >> 5;
    int lane = threadIdx.x & 31;
    int g    = lane >> 2;        // edge group 0..7
    int q    = lane & 3;         // quad: dims q*4 .. q*4+3

    int ptr = g_ptr[n];
    int deg = g_cnt[n];

    float4 acc = make_float4(0.f, 0.f, 0.f, 0.f);
    if (g == 0)                                              // self-loop
        acc = *reinterpret_cast<const float4*>(&g_g1[n * D_HID + q * 4]);

    int i = g;
    for (; i + 8 < deg; i += 16) {
        int s0 = g_csr_src[ptr + i];
        int s1 = g_csr_src[ptr + i + 8];
        float4 r0 = *reinterpret_cast<const float4*>(&g_g1[s0 * D_HID + q * 4]);
        float4 r1 = *reinterpret_cast<const float4*>(&g_g1[s1 * D_HID + q * 4]);
        acc.x += r0.x + r1.x; acc.y += r0.y + r1.y;
        acc.z += r0.z + r1.z; acc.w += r0.w + r1.w;
    }
    if (i < deg) {
        int s = g_csr_src[ptr + i];
        float4 r = *reinterpret_cast<const float4*>(&g_g1[s * D_HID + q * 4]);
        acc.x += r.x; acc.y += r.y; acc.z += r.z; acc.w += r.w;
    }

#pragma unroll
    for (int off = 16; off >= 4; off >>= 1) {
        acc.x += __shfl_down_sync(0xffffffffu, acc.x, off);
        acc.y += __shfl_down_sync(0xffffffffu, acc.y, off);
        acc.z += __shfl_down_sync(0xffffffffu, acc.z, off);
        acc.w += __shfl_down_sync(0xffffffffu, acc.w, off);
    }
    float dv = g_dinv[n];
    float4 bq = *reinterpret_cast<const float4*>(&b1[q * 4]);
    float t0 = fmaxf(fmaf(dv, acc.x, bq.x), 0.f);
    float t1 = fmaxf(fmaf(dv, acc.y, bq.y), 0.f);
    float t2 = fmaxf(fmaf(dv, acc.z, bq.z), 0.f);
    float t3 = fmaxf(fmaf(dv, acc.w, bq.w), 0.f);
    float4 w0 = *reinterpret_cast<const float4*>(&W2[q * 8]);
    float4 w1 = *reinterpret_cast<const float4*>(&W2[q * 8 + 4]);
    float p0 = fmaf(t0, w0.x, fmaf(t1, w0.z, fmaf(t2, w1.x, t3 * w1.z)));
    float p1 = fmaf(t0, w0.y, fmaf(t1, w0.w, fmaf(t2, w1.y, t3 * w1.w)));
    p0 += __shfl_down_sync(0xffffffffu, p0, 2);
    p1 += __shfl_down_sync(0xffffffffu, p1, 2);
    p0 += __shfl_down_sync(0xffffffffu, p0, 1);
    p1 += __shfl_down_sync(0xffffffffu, p1, 1);
    if (lane == 0)
        *reinterpret_cast<float2*>(&g_g2[n * 2]) = make_float2(p0 * dv, p1 * dv);
}

// ---- 6) layer-2 gather + fused log_softmax + g_cnt self-reset ----
__global__ __launch_bounds__(256) void k_gather2(const float* __restrict__ b2,
                                                 float* __restrict__ out) {
    int n    = (blockIdx.x * blockDim.x + threadIdx.x) >> 5;
    int lane = threadIdx.x & 31;
    int c = lane & 1;

    int ptr = g_ptr[n];
    int deg = g_cnt[n];

    float acc = (lane < 2) ? g_g2[n * 2 + c] : 0.f;          // self-loop
    int i = lane >> 1;
    for (; i + 16 < deg; i += 32) {
        int s0 = g_csr_src[ptr + i];
        int s1 = g_csr_src[ptr + i + 16];
        acc += g_g2[s0 * 2 + c] + g_g2[s1 * 2 + c];
    }
    if (i < deg) {
        int s = g_csr_src[ptr + i];
        acc += g_g2[s * 2 + c];
    }
#pragma unroll
    for (int off = 16; off >= 2; off >>= 1)
        acc += __shfl_down_sync(0xffffffffu, acc, off);       // parity preserved

    float dv = g_dinv[n];
    float z = fmaf(dv, acc, __ldg(&b2[c]));                   // valid on lanes 0,1
    float z0 = __shfl_sync(0xffffffffu, z, 0);
    float z1 = __shfl_sync(0xffffffffu, z, 1);
    if (lane == 0) {
        float m = fmaxf(z0, z1);
        float lse = m + logf(expf(z0 - m) + expf(z1 - m));
        *reinterpret_cast<float2*>(&out[n * 2]) = make_float2(z0 - lse, z1 - lse);
        g_cnt[n] = 0;                                         // reset for next replay
    }
}

extern "C" void kernel_launch(void* const* d_in, const int* in_sizes, int n_in,
                              void* d_out, int out_size) {
    const float* x      = (const float*)d_in[0];
    const int*   ei     = (const int*)d_in[1];      // int32 [2, E]
    const int*   ei_src = ei;
    const int*   ei_dst = ei + N_EDGES;
    const float* W1     = (const float*)d_in[2];
    const float* b1     = (const float*)d_in[3];
    const float* W2     = (const float*)d_in[4];
    const float* b2     = (const float*)d_in[5];
    float* out = (float*)d_out;

    const int TB = 256;
    k_cnt    <<<(N_EDGES + TB - 1) / TB, TB>>>(ei_dst);
    k_scan   <<<NB_SCAN, TB>>>();
    k_gemm1  <<<N_NODES / 16, 256>>>(x, W1);
    k_fill   <<<(N_EDGES + TB - 1) / TB, TB>>>(ei_src, ei_dst);
    k_gather1<<<N_NODES / 8, 256>>>(b1, W2);
    k_gather2<<<N_NODES / 8, 256>>>(b2, out);
}

// round 11
// speedup vs baseline: 1.2929x; 1.1021x over previous
#include <cuda_runtime.h>

#define N_NODES 100000
#define N_EDGES 3200000
#define D_IN    128
#define D_HID   16
#define N_CLS   2

#define NB_SCAN 391          // 391 * 256 = 100096 >= N_NODES
#define NB_FILL 12500        // 12500 * 256 = 3.2M edges
#define NB_GEMM 6250         // 6250 * 16 nodes
#define NB_FUSE (NB_FILL + NB_GEMM)

// ---- scratch (static device memory; no runtime allocation) ----
// g_cnt starts zero (module init) and is re-zeroed by k_gather2 every pass.
__device__ __align__(128) int   g_cnt [N_NODES];
__device__ __align__(128) int   g_ptr [N_NODES];
__device__ __align__(128) int   g_fill[N_NODES];
__device__ __align__(128) float g_dinv[N_NODES];
__device__ __align__(128) int   g_csr_src[N_EDGES];
__device__ __align__(128) float g_g1  [N_NODES * D_HID];
__device__ __align__(128) float g_g2  [N_NODES * N_CLS];

// scan state (module-init 0; self-reset every pass)
__device__ __align__(128) int g_agg[NB_SCAN];
__device__ volatile int g_pub;
__device__ int g_fin;

// ---- 1) in-degree histogram (1 edge/thread; unused return -> RED) ----
__global__ __launch_bounds__(256) void k_cnt(const int* __restrict__ ei_dst) {
    int e = blockIdx.x * blockDim.x + threadIdx.x;
    if (e < N_EDGES) atomicAdd(&g_cnt[ei_dst[e]], 1);
}

// ---- 2) single-kernel exclusive scan: publish-all + spin + parallel sum ----
__global__ __launch_bounds__(256) void k_scan() {
    __shared__ int wsum[8];
    __shared__ int red[8];
    __shared__ int s_base;
    __shared__ int s_last;
    int b = blockIdx.x, t = threadIdx.x;
    int i = b * 256 + t;
    int lane = t & 31, w = t >> 5;

    int v = (i < N_NODES) ? g_cnt[i] : 0;

    int x = v;
#pragma unroll
    for (int off = 1; off < 32; off <<= 1) {
        int y = __shfl_up_sync(0xffffffffu, x, off);
        if (lane >= off) x += y;
    }
    if (lane == 31) wsum[w] = x;
    __syncthreads();
    if (w == 0) {
        int s = (lane < 8) ? wsum[lane] : 0;
#pragma unroll
        for (int off = 1; off < 8; off <<= 1) {
            int y = __shfl_up_sync(0xffffffffu, s, off);
            if (lane >= off) s += y;
        }
        if (lane < 8) wsum[lane] = s;
    }
    __syncthreads();
    int incl  = x + (w > 0 ? wsum[w - 1] : 0);
    int total = wsum[7];

    if (t == 0) {
        g_agg[b] = total;
        __threadfence();
        atomicAdd((int*)&g_pub, 1);
        while (g_pub < NB_SCAN) { }
    }
    __syncthreads();

    int part = 0;
    for (int j = t; j < b; j += 256) part += g_agg[j];
#pragma unroll
    for (int off = 16; off >= 1; off >>= 1)
        part += __shfl_down_sync(0xffffffffu, part, off);
    if (lane == 0) red[w] = part;
    __syncthreads();
    if (t == 0) {
        int base = 0;
#pragma unroll
        for (int k = 0; k < 8; k++) base += red[k];
        s_base = base;
    }
    __syncthreads();

    if (i < N_NODES) {
        int excl = s_base + incl - v;
        g_ptr[i]  = excl;
        g_fill[i] = excl;
        g_dinv[i] = rsqrtf((float)(v + 1));      // +1 self-loop
    }

    __syncthreads();
    if (t == 0) s_last = (atomicAdd(&g_fin, 1) == NB_SCAN - 1);
    __syncthreads();
    if (s_last && t == 0) { g_fin = 0; g_pub = 0; }
}

// ---- 3) FUSED: gemm1 role (every 3rd block) + fill role (the rest) ----
// Roles are independent (gemm1: reads x,W1,g_dinv -> writes g_g1;
// fill: reads ei,g_fill cursor -> writes g_csr_src) and stress disjoint
// pipes (DRAM streaming vs L2 atomics), so they overlap on-chip.
__global__ __launch_bounds__(256) void k_fused(const float* __restrict__ x,
                                               const float* __restrict__ W1,
                                               const int* __restrict__ ei_src,
                                               const int* __restrict__ ei_dst) {
    __shared__ float Ws[D_IN * D_HID];
    __shared__ float Xs[16][D_IN + 1];

    int bx = blockIdx.x;
    int third = bx / 3;
    int tid = threadIdx.x;

    if (bx % 3 == 0) {
        // ---- gemm1 role: tile = third (0..6249) ----
        int nodeBase = third * 16;

        for (int i = tid; i < D_IN * D_HID; i += 256) Ws[i] = W1[i];
        for (int i = tid; i < 16 * D_IN; i += 256) {
            int r = i >> 7, c = i & 127;
            Xs[r][c] = x[(nodeBase + r) * D_IN + c];
        }
        __syncthreads();

        int node = tid >> 4, col = tid & 15;
        float acc = 0.f;
#pragma unroll
        for (int k = 0; k < D_IN; k++) acc += Xs[node][k] * Ws[k * D_HID + col];

        int gn = nodeBase + node;
        g_g1[gn * D_HID + col] = acc * g_dinv[gn];
    } else {
        // ---- fill role: fill block id 0..12499 ----
        int fb = bx - third - 1;
        int e = fb * 256 + tid;
        int pos = atomicAdd(&g_fill[ei_dst[e]], 1);
        g_csr_src[pos] = ei_src[e];
    }
}

// ---- 4) layer-1 gather + fused layer-2 node GEMM ----
// warp per node; 4 lanes per edge (one coalesced 64B row), 8 edges/iter, x2 unroll.
__global__ __launch_bounds__(256) void k_gather1(const float* __restrict__ b1,
                                                 const float* __restrict__ W2) {
    int n    = (blockIdx.x * blockDim.x + threadIdx.x) >> 5;
    int lane = threadIdx.x & 31;
    int g    = lane >> 2;        // edge group 0..7
    int q    = lane & 3;         // quad: dims q*4 .. q*4+3

    int ptr = g_ptr[n];
    int deg = g_cnt[n];

    float4 acc = make_float4(0.f, 0.f, 0.f, 0.f);
    if (g == 0)                                              // self-loop
        acc = *reinterpret_cast<const float4*>(&g_g1[n * D_HID + q * 4]);

    int i = g;
    for (; i + 8 < deg; i += 16) {
        int s0 = g_csr_src[ptr + i];
        int s1 = g_csr_src[ptr + i + 8];
        float4 r0 = *reinterpret_cast<const float4*>(&g_g1[s0 * D_HID + q * 4]);
        float4 r1 = *reinterpret_cast<const float4*>(&g_g1[s1 * D_HID + q * 4]);
        acc.x += r0.x + r1.x; acc.y += r0.y + r1.y;
        acc.z += r0.z + r1.z; acc.w += r0.w + r1.w;
    }
    if (i < deg) {
        int s = g_csr_src[ptr + i];
        float4 r = *reinterpret_cast<const float4*>(&g_g1[s * D_HID + q * 4]);
        acc.x += r.x; acc.y += r.y; acc.z += r.z; acc.w += r.w;
    }

#pragma unroll
    for (int off = 16; off >= 4; off >>= 1) {
        acc.x += __shfl_down_sync(0xffffffffu, acc.x, off);
        acc.y += __shfl_down_sync(0xffffffffu, acc.y, off);
        acc.z += __shfl_down_sync(0xffffffffu, acc.z, off);
        acc.w += __shfl_down_sync(0xffffffffu, acc.w, off);
    }
    float dv = g_dinv[n];
    float4 bq = *reinterpret_cast<const float4*>(&b1[q * 4]);
    float t0 = fmaxf(fmaf(dv, acc.x, bq.x), 0.f);
    float t1 = fmaxf(fmaf(dv, acc.y, bq.y), 0.f);
    float t2 = fmaxf(fmaf(dv, acc.z, bq.z), 0.f);
    float t3 = fmaxf(fmaf(dv, acc.w, bq.w), 0.f);
    float4 w0 = *reinterpret_cast<const float4*>(&W2[q * 8]);
    float4 w1 = *reinterpret_cast<const float4*>(&W2[q * 8 + 4]);
    float p0 = fmaf(t0, w0.x, fmaf(t1, w0.z, fmaf(t2, w1.x, t3 * w1.z)));
    float p1 = fmaf(t0, w0.y, fmaf(t1, w0.w, fmaf(t2, w1.y, t3 * w1.w)));
    p0 += __shfl_down_sync(0xffffffffu, p0, 2);
    p1 += __shfl_down_sync(0xffffffffu, p1, 2);
    p0 += __shfl_down_sync(0xffffffffu, p0, 1);
    p1 += __shfl_down_sync(0xffffffffu, p1, 1);
    if (lane == 0)
        *reinterpret_cast<float2*>(&g_g2[n * 2]) = make_float2(p0 * dv, p1 * dv);
}

// ---- 5) layer-2 gather + fused log_softmax + g_cnt self-reset ----
__global__ __launch_bounds__(256) void k_gather2(const float* __restrict__ b2,
                                                 float* __restrict__ out) {
    int n    = (blockIdx.x * blockDim.x + threadIdx.x) >> 5;
    int lane = threadIdx.x & 31;
    int c = lane & 1;

    int ptr = g_ptr[n];
    int deg = g_cnt[n];

    float acc = (lane < 2) ? g_g2[n * 2 + c] : 0.f;          // self-loop
    int i = lane >> 1;
    for (; i + 16 < deg; i += 32) {
        int s0 = g_csr_src[ptr + i];
        int s1 = g_csr_src[ptr + i + 16];
        acc += g_g2[s0 * 2 + c] + g_g2[s1 * 2 + c];
    }
    if (i < deg) {
        int s = g_csr_src[ptr + i];
        acc += g_g2[s * 2 + c];
    }
#pragma unroll
    for (int off = 16; off >= 2; off >>= 1)
        acc += __shfl_down_sync(0xffffffffu, acc, off);       // parity preserved

    float dv = g_dinv[n];
    float z = fmaf(dv, acc, __ldg(&b2[c]));                   // valid on lanes 0,1
    float z0 = __shfl_sync(0xffffffffu, z, 0);
    float z1 = __shfl_sync(0xffffffffu, z, 1);
    if (lane == 0) {
        float m = fmaxf(z0, z1);
        float lse = m + logf(expf(z0 - m) + expf(z1 - m));
        *reinterpret_cast<float2*>(&out[n * 2]) = make_float2(z0 - lse, z1 - lse);
        g_cnt[n] = 0;                                         // reset for next replay
    }
}

extern "C" void kernel_launch(void* const* d_in, const int* in_sizes, int n_in,
                              void* d_out, int out_size) {
    const float* x      = (const float*)d_in[0];
    const int*   ei     = (const int*)d_in[1];      // int32 [2, E]
    const int*   ei_src = ei;
    const int*   ei_dst = ei + N_EDGES;
    const float* W1     = (const float*)d_in[2];
    const float* b1     = (const float*)d_in[3];
    const float* W2     = (const float*)d_in[4];
    const float* b2     = (const float*)d_in[5];
    float* out = (float*)d_out;

    const int TB = 256;
    k_cnt    <<<(N_EDGES + TB - 1) / TB, TB>>>(ei_dst);
    k_scan   <<<NB_SCAN, TB>>>();
    k_fused  <<<NB_FUSE, TB>>>(x, W1, ei_src, ei_dst);
    k_gather1<<<N_NODES / 8, 256>>>(b1, W2);
    k_gather2<<<N_NODES / 8, 256>>>(b2, out);
}